// round 1
// baseline (speedup 1.0000x reference)
#include <cuda_runtime.h>
#include <math.h>

#define BB 2
#define NN 512
#define DD 256
#define HH 256
#define HH2 128

#define JT 64          // j-rows per tile in main kernel
#define HSTR 260       // padded stride for h tile (260 % 32 = 4 -> conflict-free)
#define NTHREADS 256

// Scratch (allocation-free rule: __device__ globals)
__device__ float g_left[BB * NN * HH];   // left + b1 folded in
__device__ float g_right[BB * NN * HH];

// ---------------------------------------------------------------------------
// Kernel A: left[b,n,h] = sum_d x[b,n,d]*W1[d,h] + b1[h]
//           right[b,n,h] = sum_d x[b,n,d]*W1[D+d,h]
// grid = B*N blocks of 256 threads (thread = h)
// ---------------------------------------------------------------------------
__global__ __launch_bounds__(256) void lr_kernel(
    const float* __restrict__ x, const float* __restrict__ W1,
    const float* __restrict__ b1)
{
    __shared__ float sx[DD];
    int bn = blockIdx.x;
    int h = threadIdx.x;
    sx[h] = x[bn * DD + h];
    __syncthreads();

    float l = b1[h];
    float r = 0.f;
#pragma unroll 4
    for (int d = 0; d < DD; d++) {
        float xv = sx[d];
        l = fmaf(xv, W1[d * HH + h], l);
        r = fmaf(xv, W1[(DD + d) * HH + h], r);
    }
    g_left[bn * HH + h] = l;
    g_right[bn * HH + h] = r;
}

// ---------------------------------------------------------------------------
// Kernel B: per (b,i) CTA — fused pair-MLP GEMM + edge dot + sigmoid +
// softmax(base_adj*ew + I) + p@x + @Wg + bg
// grid = (N, B), 256 threads
// ---------------------------------------------------------------------------
__global__ __launch_bounds__(NTHREADS, 1) void main_kernel(
    const float* __restrict__ x, const float* __restrict__ base_adj,
    const float* __restrict__ W2, const float* __restrict__ b2,
    const float* __restrict__ W3, const float* __restrict__ b3,
    const float* __restrict__ Wg, const float* __restrict__ bg,
    float* __restrict__ out)
{
    extern __shared__ float smem[];
    float* sW2  = smem;                  // 256*128 = 32768 floats
    float* sH   = sW2 + HH * HH2;        // 64*260 = 16640 floats
    float* sL   = sH + JT * HSTR;        // 256
    float* sEw  = sL + HH;               // 512 (edge weights -> probs)
    float* sAgg = sEw + NN;              // 256
    float* sRed = sAgg + DD;             // 32 (reduction scratch)

    const int i = blockIdx.x;
    const int b = blockIdx.y;
    const int tid = threadIdx.x;
    const int tx = tid & 15;
    const int ty = tid >> 4;

    // Stage W2 into SMEM (float4)
    {
        const float4* W2v = (const float4*)W2;
        float4* sW2v = (float4*)sW2;
#pragma unroll
        for (int idx = tid; idx < HH * HH2 / 4; idx += NTHREADS)
            sW2v[idx] = W2v[idx];
    }
    sL[tid] = g_left[(b * NN + i) * HH + tid];
    __syncthreads();

    // per-thread constants: b2 and W3 slices for output cols tx*8..tx*8+7
    float b2v[8], w3v[8];
    {
        float4 a = *(const float4*)&b2[tx * 8];
        float4 c = *(const float4*)&b2[tx * 8 + 4];
        b2v[0]=a.x; b2v[1]=a.y; b2v[2]=a.z; b2v[3]=a.w;
        b2v[4]=c.x; b2v[5]=c.y; b2v[6]=c.z; b2v[7]=c.w;
        float4 d = *(const float4*)&W3[tx * 8];
        float4 e = *(const float4*)&W3[tx * 8 + 4];
        w3v[0]=d.x; w3v[1]=d.y; w3v[2]=d.z; w3v[3]=d.w;
        w3v[4]=e.x; w3v[5]=e.y; w3v[6]=e.z; w3v[7]=e.w;
    }
    const float bias3 = b3[0];

    // ---- pair-MLP over j tiles ----
    for (int jt = 0; jt < NN / JT; jt++) {
        const int j0 = jt * JT;

        // Stage 1: h tile = relu(left + right_j) into SMEM (row jj, col tid)
        const float* rbase = g_right + ((size_t)(b * NN + j0)) * HH;
#pragma unroll 4
        for (int jj = 0; jj < JT; jj++) {
            float v = sL[tid] + rbase[jj * HH + tid];
            sH[jj * HSTR + tid] = fmaxf(v, 0.f);
        }
        __syncthreads();

        // Stage 2: GEMM [64,256] x [256,128]; each thread does 4 rows x 8 cols
        float acc[4][8];
#pragma unroll
        for (int r = 0; r < 4; r++)
#pragma unroll
            for (int c = 0; c < 8; c++) acc[r][c] = 0.f;

        const float* hbase = sH + (ty * 4) * HSTR;
#pragma unroll 2
        for (int k = 0; k < HH; k++) {
            float hv[4];
#pragma unroll
            for (int r = 0; r < 4; r++) hv[r] = hbase[r * HSTR + k];
            float4 wA = *(const float4*)&sW2[k * HH2 + tx * 8];
            float4 wB = *(const float4*)&sW2[k * HH2 + tx * 8 + 4];
            float w[8] = {wA.x, wA.y, wA.z, wA.w, wB.x, wB.y, wB.z, wB.w};
#pragma unroll
            for (int r = 0; r < 4; r++)
#pragma unroll
                for (int c = 0; c < 8; c++)
                    acc[r][c] = fmaf(hv[r], w[c], acc[r][c]);
        }

        // Stage 3: relu(acc+b2) . W3, reduce over tx (16-lane shuffle), sigmoid
#pragma unroll
        for (int r = 0; r < 4; r++) {
            float p = 0.f;
#pragma unroll
            for (int c = 0; c < 8; c++) {
                float s = fmaxf(acc[r][c] + b2v[c], 0.f);
                p = fmaf(s, w3v[c], p);
            }
#pragma unroll
            for (int off = 8; off > 0; off >>= 1)
                p += __shfl_down_sync(0xffffffffu, p, off, 16);
            if (tx == 0) {
                float z = p + bias3;
                sEw[j0 + ty * 4 + r] = 1.f / (1.f + expf(-z));
            }
        }
        __syncthreads();
    }

    // ---- softmax over j of base_adj*ew + I ----
    float v0, v1;
    {
        const float* ba = base_adj + ((size_t)(b * NN + i)) * NN;
        int ja = tid, jb = tid + 256;
        v0 = ba[ja] * sEw[ja] + (ja == i ? 1.f : 0.f);
        v1 = ba[jb] * sEw[jb] + (jb == i ? 1.f : 0.f);
    }
    // block max
    float m = fmaxf(v0, v1);
#pragma unroll
    for (int off = 16; off > 0; off >>= 1)
        m = fmaxf(m, __shfl_xor_sync(0xffffffffu, m, off));
    if ((tid & 31) == 0) sRed[tid >> 5] = m;
    __syncthreads();
    if (tid == 0) {
        float mm = sRed[0];
#pragma unroll
        for (int w = 1; w < 8; w++) mm = fmaxf(mm, sRed[w]);
        sRed[0] = mm;
    }
    __syncthreads();
    m = sRed[0];
    __syncthreads();

    float e0 = expf(v0 - m);
    float e1 = expf(v1 - m);
    float s = e0 + e1;
#pragma unroll
    for (int off = 16; off > 0; off >>= 1)
        s += __shfl_xor_sync(0xffffffffu, s, off);
    if ((tid & 31) == 0) sRed[tid >> 5] = s;
    __syncthreads();
    if (tid == 0) {
        float ss = 0.f;
#pragma unroll
        for (int w = 0; w < 8; w++) ss += sRed[w];
        sRed[0] = ss;
    }
    __syncthreads();
    const float inv = 1.f / sRed[0];
    sEw[tid] = e0 * inv;
    sEw[tid + 256] = e1 * inv;
    __syncthreads();

    // ---- agg[d] = sum_j p[j] * x[b,j,d]  (thread = d) ----
    {
        const float* xb = x + (size_t)b * NN * DD;
        float a0 = 0.f, a1 = 0.f, a2 = 0.f, a3 = 0.f;
#pragma unroll 2
        for (int j = 0; j < NN; j += 4) {
            a0 = fmaf(sEw[j],     xb[(j)     * DD + tid], a0);
            a1 = fmaf(sEw[j + 1], xb[(j + 1) * DD + tid], a1);
            a2 = fmaf(sEw[j + 2], xb[(j + 2) * DD + tid], a2);
            a3 = fmaf(sEw[j + 3], xb[(j + 3) * DD + tid], a3);
        }
        sAgg[tid] = (a0 + a1) + (a2 + a3);
    }
    __syncthreads();

    // ---- out[h] = sum_d agg[d]*Wg[d,h] + bg[h]  (thread = h) ----
    {
        float o0 = bg[tid], o1 = 0.f, o2 = 0.f, o3 = 0.f;
#pragma unroll 2
        for (int d = 0; d < DD; d += 4) {
            o0 = fmaf(sAgg[d],     Wg[(d)     * HH + tid], o0);
            o1 = fmaf(sAgg[d + 1], Wg[(d + 1) * HH + tid], o1);
            o2 = fmaf(sAgg[d + 2], Wg[(d + 2) * HH + tid], o2);
            o3 = fmaf(sAgg[d + 3], Wg[(d + 3) * HH + tid], o3);
        }
        out[((size_t)(b * NN + i)) * HH + tid] = (o0 + o1) + (o2 + o3);
    }
}

// ---------------------------------------------------------------------------
extern "C" void kernel_launch(void* const* d_in, const int* in_sizes, int n_in,
                              void* d_out, int out_size)
{
    const float* x        = (const float*)d_in[0];
    const float* base_adj = (const float*)d_in[1];
    const float* W1       = (const float*)d_in[2];
    const float* b1       = (const float*)d_in[3];
    const float* W2       = (const float*)d_in[4];
    const float* b2       = (const float*)d_in[5];
    const float* W3       = (const float*)d_in[6];
    const float* b3       = (const float*)d_in[7];
    const float* Wg       = (const float*)d_in[8];
    const float* bg       = (const float*)d_in[9];
    float* out = (float*)d_out;

    const size_t smem_bytes =
        (size_t)(HH * HH2 + JT * HSTR + HH + NN + DD + 32) * sizeof(float);
    cudaFuncSetAttribute(main_kernel,
                         cudaFuncAttributeMaxDynamicSharedMemorySize,
                         (int)smem_bytes);

    lr_kernel<<<BB * NN, 256>>>(x, W1, b1);
    main_kernel<<<dim3(NN, BB), NTHREADS, smem_bytes>>>(
        x, base_adj, W2, b2, W3, b3, Wg, bg, out);
}

// round 3
// speedup vs baseline: 3.5327x; 3.5327x over previous
#include <cuda_runtime.h>
#include <cuda_bf16.h>
#include <math.h>
#include <stdint.h>

#define BB 2
#define NN 512
#define DD 256
#define HH 256
#define HH2 128
#define NTHREADS 256

// SMEM byte offsets
#define OFF_RED   64
#define OFF_BW    256      // float2[128]: {b2[c], W3[c]}
#define OFF_LF    1280     // float[256]: left row i
#define OFF_EW    2304     // float[512]: edge weights -> probs
#define OFF_AGG   4352     // float[256]
#define OFF_B     8192     // 64KB: W2 bf16 [k=256][n words=64] swizzled
#define OFF_AH    73728    // 64KB: A hi tile [j=128][k words=128] swizzled
#define OFF_AL    139264   // 64KB: A lo tile
#define SMEM_TOTAL 204800

// Scratch (__device__ globals: allocation-free rule)
__device__ float    g_left[BB * NN * HH];
__device__ float    g_right[BB * NN * HH];
__device__ uint32_t gB_img[16384];   // 64KB swizzled W2 bf16 image

// ---------------------------------------------------------------------------
// helpers
// ---------------------------------------------------------------------------
__device__ __forceinline__ uint32_t smem_u32(const void* p) {
    uint32_t a;
    asm("{ .reg .u64 t; cvta.to.shared.u64 t, %1; cvt.u32.u64 %0, t; }"
        : "=r"(a) : "l"(p));
    return a;
}
__device__ __forceinline__ uint32_t pack_bf16x2(float lo, float hi) {
    uint32_t r;
    asm("cvt.rn.satfinite.bf16x2.f32 %0, %1, %2;" : "=r"(r) : "f"(hi), "f"(lo));
    return r;
}
__device__ __forceinline__ void ldsm_x4(uint32_t* r, uint32_t addr) {
    asm volatile("ldmatrix.sync.aligned.m8n8.x4.shared.b16 {%0,%1,%2,%3}, [%4];"
                 : "=r"(r[0]), "=r"(r[1]), "=r"(r[2]), "=r"(r[3]) : "r"(addr));
}
__device__ __forceinline__ void ldsm_x4_t(uint32_t* r, uint32_t addr) {
    asm volatile("ldmatrix.sync.aligned.m8n8.x4.trans.shared.b16 {%0,%1,%2,%3}, [%4];"
                 : "=r"(r[0]), "=r"(r[1]), "=r"(r[2]), "=r"(r[3]) : "r"(addr));
}
__device__ __forceinline__ void mma16816(float* d, const uint32_t* a,
                                         const uint32_t* b) {
    asm volatile(
        "mma.sync.aligned.m16n8k16.row.col.f32.bf16.bf16.f32 "
        "{%0,%1,%2,%3}, {%4,%5,%6,%7}, {%8,%9}, {%0,%1,%2,%3};"
        : "+f"(d[0]), "+f"(d[1]), "+f"(d[2]), "+f"(d[3])
        : "r"(a[0]), "r"(a[1]), "r"(a[2]), "r"(a[3]), "r"(b[0]), "r"(b[1]));
}

// ---------------------------------------------------------------------------
// Kernel A: left/right projections (left has b1 folded in)
// ---------------------------------------------------------------------------
__global__ __launch_bounds__(256) void lr_kernel(
    const float* __restrict__ x, const float* __restrict__ W1,
    const float* __restrict__ b1)
{
    __shared__ float sx[DD];
    int bn = blockIdx.x;
    int h = threadIdx.x;
    sx[h] = x[bn * DD + h];
    __syncthreads();
    float l = b1[h], r = 0.f;
#pragma unroll 4
    for (int d = 0; d < DD; d++) {
        float xv = sx[d];
        l = fmaf(xv, W1[d * HH + h], l);
        r = fmaf(xv, W1[(DD + d) * HH + h], r);
    }
    g_left[bn * HH + h] = l;
    g_right[bn * HH + h] = r;
}

// ---------------------------------------------------------------------------
// Kernel P: swizzled bf16 image of W2 [k=256 rows][64 words of n]
// word w covers n=2w,2w+1; addr = k*256 + ((w>>2 ^ (k&7))<<4) + (w&3)*4
// ---------------------------------------------------------------------------
__global__ __launch_bounds__(256) void bprep_kernel(const float* __restrict__ W2)
{
    int idx = blockIdx.x * 256 + threadIdx.x;   // 0..16383
    int k = idx >> 6;
    int w = idx & 63;
    float2 v = ((const float2*)W2)[k * 64 + w];
    uint32_t packed = pack_bf16x2(v.x, v.y);
    uint32_t off = (uint32_t)(k * 256 + ((((w >> 2) ^ (k & 7)) << 4)) + (w & 3) * 4);
    gB_img[off >> 2] = packed;
}

// ---------------------------------------------------------------------------
// Kernel B: per (b,i) — mma.sync pair-MLP + edge dot + sigmoid + softmax +
// p@x + @Wg + bg
// ---------------------------------------------------------------------------
__global__ __launch_bounds__(NTHREADS, 1)
void main_kernel(
    const float* __restrict__ x, const float* __restrict__ base_adj,
    const float* __restrict__ b2, const float* __restrict__ W3,
    const float* __restrict__ b3, const float* __restrict__ Wg,
    const float* __restrict__ bg, float* __restrict__ out)
{
    extern __shared__ char smem[];
    const uint32_t sbase = smem_u32(smem);
    const int i = blockIdx.x;
    const int b = blockIdx.y;
    const int tid = threadIdx.x;
    const int wid = tid >> 5;
    const int lid = tid & 31;

    float*  sRed = (float*)(smem + OFF_RED);
    float2* sBW  = (float2*)(smem + OFF_BW);
    float*  sLf  = (float*)(smem + OFF_LF);
    float*  sEw  = (float*)(smem + OFF_EW);
    float*  sAgg = (float*)(smem + OFF_AGG);

    // Stage B tile (pre-swizzled image) + left row + b2/W3 pairs
    {
        const uint4* src = (const uint4*)gB_img;
        uint4* dst = (uint4*)(smem + OFF_B);
#pragma unroll
        for (int t = tid; t < 4096; t += NTHREADS) dst[t] = src[t];
    }
    sLf[tid] = g_left[(b * NN + i) * HH + tid];
    if (tid < HH2) sBW[tid] = make_float2(b2[tid], W3[tid]);

    const float bias3 = b3[0];

    // A-build constants: thread covers word kp (k=2kp,2kp+1), j parity jhalf
    const uint32_t jhalf = (uint32_t)tid >> 7;
    const uint32_t kp = (uint32_t)tid & 127;
    const int k2 = (int)kp * 2;
    __syncthreads();
    const float lf0 = sLf[k2], lf1 = sLf[k2 + 1];

    // MMA addressing constants
    const int gid = lid >> 2, tig = lid & 3;
    const uint32_t hi16 = (uint32_t)lid >> 4;
    const int jm = wid * 16;
    const int a_j = jm + (lid & 7) + (((lid >> 3) & 1) << 3);
    const uint32_t aH_row = sbase + OFF_AH + a_j * 512;
    const uint32_t aL_row = sbase + OFF_AL + a_j * 512;
    const uint32_t a_xor = (uint32_t)(a_j & 7) << 4;
    const int b_k = (lid & 7) + (((lid >> 3) & 1) << 3);
    const uint32_t b_row0 = sbase + OFF_B + b_k * 256;
    const uint32_t b_xor = (uint32_t)(b_k & 7) << 4;

    // ---- 4 j-tiles of 128 ----
    for (int jt = 0; jt < 4; jt++) {
        const int j0 = jt * 128;
        const float* rbase = g_right + ((size_t)(b * NN + j0)) * HH;

        if (jt) __syncthreads();   // previous tile's reads done

        // Build A hi/lo tiles
#pragma unroll 4
        for (int it = 0; it < 64; it++) {
            int j = it * 2 + (int)jhalf;
            float2 rv = *(const float2*)&rbase[j * HH + k2];
            float v0 = fmaxf(lf0 + rv.x, 0.f);
            float v1 = fmaxf(lf1 + rv.y, 0.f);
            uint32_t hi = pack_bf16x2(v0, v1);
            float h0 = __uint_as_float(hi << 16);
            float h1 = __uint_as_float(hi & 0xffff0000u);
            uint32_t lo = pack_bf16x2(v0 - h0, v1 - h1);
            uint32_t off = (uint32_t)(j * 512 +
                           ((((kp >> 2) ^ (uint32_t)(j & 7)) << 4)) + (kp & 3) * 4);
            *(uint32_t*)(smem + OFF_AH + off) = hi;
            *(uint32_t*)(smem + OFF_AL + off) = lo;
        }
        __syncthreads();

        // ---- warp GEMM: D[16,128] += (A_hi + A_lo)[16,256] @ B[256,128] ----
        float acc[16][4];
#pragma unroll
        for (int nt = 0; nt < 16; nt++)
#pragma unroll
            for (int c = 0; c < 4; c++) acc[nt][c] = 0.f;

#pragma unroll 2
        for (int s = 0; s < 16; s++) {
            uint32_t ah[4], al[4];
            uint32_t achunk = (uint32_t)((2 * s + (int)hi16) << 4) ^ a_xor;
            ldsm_x4(ah, aH_row + achunk);
            ldsm_x4(al, aL_row + achunk);
            uint32_t brow = b_row0 + (uint32_t)s * 4096;
#pragma unroll
            for (int np = 0; np < 8; np++) {
                uint32_t bb[4];
                uint32_t baddr = brow +
                    ((uint32_t)(((np << 1) + (int)hi16) << 4) ^ b_xor);
                ldsm_x4_t(bb, baddr);
                mma16816(acc[np * 2],     ah, &bb[0]);
                mma16816(acc[np * 2],     al, &bb[0]);
                mma16816(acc[np * 2 + 1], ah, &bb[2]);
                mma16816(acc[np * 2 + 1], al, &bb[2]);
            }
        }

        // ---- epilogue: z[row] = sum_c relu(D+b2)[c]*W3[c], quad-reduced ----
        float z0 = 0.f, z1 = 0.f;
#pragma unroll
        for (int nt = 0; nt < 16; nt++) {
            int c0 = nt * 8 + tig * 2;
            float2 bw0 = sBW[c0];
            float2 bw1 = sBW[c0 + 1];
            z0 = fmaf(fmaxf(acc[nt][0] + bw0.x, 0.f), bw0.y, z0);
            z0 = fmaf(fmaxf(acc[nt][1] + bw1.x, 0.f), bw1.y, z0);
            z1 = fmaf(fmaxf(acc[nt][2] + bw0.x, 0.f), bw0.y, z1);
            z1 = fmaf(fmaxf(acc[nt][3] + bw1.x, 0.f), bw1.y, z1);
        }
        z0 += __shfl_xor_sync(0xffffffffu, z0, 1);
        z0 += __shfl_xor_sync(0xffffffffu, z0, 2);
        z1 += __shfl_xor_sync(0xffffffffu, z1, 1);
        z1 += __shfl_xor_sync(0xffffffffu, z1, 2);
        if (tig == 0) {
            sEw[j0 + jm + gid]     = 1.f / (1.f + expf(-(z0 + bias3)));
            sEw[j0 + jm + gid + 8] = 1.f / (1.f + expf(-(z1 + bias3)));
        }
    }
    __syncthreads();

    // ---- softmax over j of base_adj*ew + I ----
    float v0, v1;
    {
        const float* ba = base_adj + ((size_t)(b * NN + i)) * NN;
        int ja = tid, jb = tid + 256;
        v0 = ba[ja] * sEw[ja] + (ja == i ? 1.f : 0.f);
        v1 = ba[jb] * sEw[jb] + (jb == i ? 1.f : 0.f);
    }
    float m = fmaxf(v0, v1);
#pragma unroll
    for (int off = 16; off > 0; off >>= 1)
        m = fmaxf(m, __shfl_xor_sync(0xffffffffu, m, off));
    if (lid == 0) sRed[wid] = m;
    __syncthreads();
    if (tid == 0) {
        float mm = sRed[0];
#pragma unroll
        for (int w = 1; w < 8; w++) mm = fmaxf(mm, sRed[w]);
        sRed[0] = mm;
    }
    __syncthreads();
    m = sRed[0];
    __syncthreads();

    float e0 = expf(v0 - m);
    float e1 = expf(v1 - m);
    float s = e0 + e1;
#pragma unroll
    for (int off = 16; off > 0; off >>= 1)
        s += __shfl_xor_sync(0xffffffffu, s, off);
    if (lid == 0) sRed[wid] = s;
    __syncthreads();
    if (tid == 0) {
        float ss = 0.f;
#pragma unroll
        for (int w = 0; w < 8; w++) ss += sRed[w];
        sRed[0] = ss;
    }
    __syncthreads();
    const float inv = 1.f / sRed[0];
    sEw[tid] = e0 * inv;
    sEw[tid + 256] = e1 * inv;
    __syncthreads();

    // ---- agg[d] = sum_j p[j] * x[b,j,d] ----
    {
        const float* xb = x + (size_t)b * NN * DD;
        float a0 = 0.f, a1 = 0.f, a2 = 0.f, a3 = 0.f;
#pragma unroll 2
        for (int j = 0; j < NN; j += 4) {
            a0 = fmaf(sEw[j],     xb[(j)     * DD + tid], a0);
            a1 = fmaf(sEw[j + 1], xb[(j + 1) * DD + tid], a1);
            a2 = fmaf(sEw[j + 2], xb[(j + 2) * DD + tid], a2);
            a3 = fmaf(sEw[j + 3], xb[(j + 3) * DD + tid], a3);
        }
        sAgg[tid] = (a0 + a1) + (a2 + a3);
    }
    __syncthreads();

    // ---- out[h] = sum_d agg[d]*Wg[d,h] + bg[h] ----
    {
        float o0 = bg[tid], o1 = 0.f, o2 = 0.f, o3 = 0.f;
#pragma unroll 2
        for (int d = 0; d < DD; d += 4) {
            o0 = fmaf(sAgg[d],     Wg[(d)     * HH + tid], o0);
            o1 = fmaf(sAgg[d + 1], Wg[(d + 1) * HH + tid], o1);
            o2 = fmaf(sAgg[d + 2], Wg[(d + 2) * HH + tid], o2);
            o3 = fmaf(sAgg[d + 3], Wg[(d + 3) * HH + tid], o3);
        }
        out[((size_t)(b * NN + i)) * HH + tid] = (o0 + o1) + (o2 + o3);
    }
}

// ---------------------------------------------------------------------------
extern "C" void kernel_launch(void* const* d_in, const int* in_sizes, int n_in,
                              void* d_out, int out_size)
{
    const float* x        = (const float*)d_in[0];
    const float* base_adj = (const float*)d_in[1];
    const float* W1       = (const float*)d_in[2];
    const float* b1       = (const float*)d_in[3];
    const float* W2       = (const float*)d_in[4];
    const float* b2       = (const float*)d_in[5];
    const float* W3       = (const float*)d_in[6];
    const float* b3       = (const float*)d_in[7];
    const float* Wg       = (const float*)d_in[8];
    const float* bg       = (const float*)d_in[9];
    float* out = (float*)d_out;

    cudaFuncSetAttribute(main_kernel,
                         cudaFuncAttributeMaxDynamicSharedMemorySize,
                         SMEM_TOTAL);

    bprep_kernel<<<64, 256>>>(W2);
    lr_kernel<<<BB * NN, 256>>>(x, W1, b1);
    main_kernel<<<dim3(NN, BB), NTHREADS, SMEM_TOTAL>>>(
        x, base_adj, b2, W3, b3, Wg, bg, out);
}

// round 4
// speedup vs baseline: 5.7732x; 1.6342x over previous
#include <cuda_runtime.h>
#include <cuda_fp16.h>
#include <math.h>
#include <stdint.h>

#define BB 2
#define NN 512
#define DD 256
#define HH 256
#define HH2 128
#define NTHREADS 256

// SMEM byte offsets
#define OFF_RED   64
#define OFF_BW    256      // float2[128]: {b2[c], W3[c]}
#define OFF_LF    1280     // float[256]: left row i
#define OFF_EW    2304     // float[512]
#define OFF_AGG   4352     // float[256]
#define OFF_ZA    5376     // float[128] partial z (wx=0)
#define OFF_ZB    5888     // float[128] partial z (wx=1)
#define OFF_B     8192     // 64KB: W2 fp16 [k=256][64 words] swizzled
#define OFF_AH    73728    // 64KB: A tile fp16 [j=128][128 words] swizzled
#define SMEM_TOTAL 139264

// Scratch (__device__ globals: allocation-free rule)
__device__ float    g_left[BB * NN * HH];
__device__ float    g_right[BB * NN * HH];
__device__ uint32_t gB_img[16384];   // 64KB swizzled W2 fp16 image

// ---------------------------------------------------------------------------
// helpers
// ---------------------------------------------------------------------------
__device__ __forceinline__ uint32_t smem_u32(const void* p) {
    uint32_t a;
    asm("{ .reg .u64 t; cvta.to.shared.u64 t, %1; cvt.u32.u64 %0, t; }"
        : "=r"(a) : "l"(p));
    return a;
}
__device__ __forceinline__ uint32_t pack_f16x2(float lo, float hi) {
    uint32_t r;
    asm("cvt.rn.f16x2.f32 %0, %1, %2;" : "=r"(r) : "f"(hi), "f"(lo));
    return r;
}
__device__ __forceinline__ void ldsm_x4(uint32_t* r, uint32_t addr) {
    asm volatile("ldmatrix.sync.aligned.m8n8.x4.shared.b16 {%0,%1,%2,%3}, [%4];"
                 : "=r"(r[0]), "=r"(r[1]), "=r"(r[2]), "=r"(r[3]) : "r"(addr));
}
__device__ __forceinline__ void ldsm_x4_t(uint32_t* r, uint32_t addr) {
    asm volatile("ldmatrix.sync.aligned.m8n8.x4.trans.shared.b16 {%0,%1,%2,%3}, [%4];"
                 : "=r"(r[0]), "=r"(r[1]), "=r"(r[2]), "=r"(r[3]) : "r"(addr));
}
__device__ __forceinline__ void mma16816(float* d, const uint32_t* a,
                                         const uint32_t* b) {
    asm volatile(
        "mma.sync.aligned.m16n8k16.row.col.f32.f16.f16.f32 "
        "{%0,%1,%2,%3}, {%4,%5,%6,%7}, {%8,%9}, {%0,%1,%2,%3};"
        : "+f"(d[0]), "+f"(d[1]), "+f"(d[2]), "+f"(d[3])
        : "r"(a[0]), "r"(a[1]), "r"(a[2]), "r"(a[3]), "r"(b[0]), "r"(b[1]));
}

// ---------------------------------------------------------------------------
// Kernel A: left/right projections, 8 rows per CTA (W1 traffic /8)
// ---------------------------------------------------------------------------
#define LR_ROWS 8
__global__ __launch_bounds__(256) void lr_kernel(
    const float* __restrict__ x, const float* __restrict__ W1,
    const float* __restrict__ b1)
{
    __shared__ float sx[LR_ROWS][DD];
    const int r0 = blockIdx.x * LR_ROWS;
    const int h = threadIdx.x;
#pragma unroll
    for (int t = 0; t < LR_ROWS; t++)
        sx[t][h] = x[(r0 + t) * DD + h];
    __syncthreads();

    float l[LR_ROWS], r[LR_ROWS];
#pragma unroll
    for (int t = 0; t < LR_ROWS; t++) { l[t] = b1[h]; r[t] = 0.f; }

#pragma unroll 2
    for (int d = 0; d < DD; d += 4) {
        float wl[4], wr[4];
#pragma unroll
        for (int q = 0; q < 4; q++) {
            wl[q] = W1[(d + q) * HH + h];
            wr[q] = W1[(DD + d + q) * HH + h];
        }
#pragma unroll
        for (int t = 0; t < LR_ROWS; t++) {
            float4 xv = *(const float4*)&sx[t][d];
            l[t] = fmaf(xv.x, wl[0], l[t]); r[t] = fmaf(xv.x, wr[0], r[t]);
            l[t] = fmaf(xv.y, wl[1], l[t]); r[t] = fmaf(xv.y, wr[1], r[t]);
            l[t] = fmaf(xv.z, wl[2], l[t]); r[t] = fmaf(xv.z, wr[2], r[t]);
            l[t] = fmaf(xv.w, wl[3], l[t]); r[t] = fmaf(xv.w, wr[3], r[t]);
        }
    }
#pragma unroll
    for (int t = 0; t < LR_ROWS; t++) {
        g_left[(r0 + t) * HH + h] = l[t];
        g_right[(r0 + t) * HH + h] = r[t];
    }
}

// ---------------------------------------------------------------------------
// Kernel P: swizzled fp16 image of W2 [k=256 rows][64 words of n]
// ---------------------------------------------------------------------------
__global__ __launch_bounds__(256) void bprep_kernel(const float* __restrict__ W2)
{
    int idx = blockIdx.x * 256 + threadIdx.x;   // 0..16383
    int k = idx >> 6;
    int w = idx & 63;
    float2 v = ((const float2*)W2)[k * 64 + w];
    uint32_t packed = pack_f16x2(v.x, v.y);
    uint32_t off = (uint32_t)(k * 256 + ((((w >> 2) ^ (k & 7)) << 4)) + (w & 3) * 4);
    gB_img[off >> 2] = packed;
}

// ---------------------------------------------------------------------------
// Kernel B: per (b,i) — mma.sync fp16 pair-MLP + edge dot + sigmoid +
// softmax + p@x + @Wg + bg
// ---------------------------------------------------------------------------
__global__ __launch_bounds__(NTHREADS, 1)
void main_kernel(
    const float* __restrict__ x, const float* __restrict__ base_adj,
    const float* __restrict__ b2, const float* __restrict__ W3,
    const float* __restrict__ b3, const float* __restrict__ Wg,
    const float* __restrict__ bg, float* __restrict__ out)
{
    extern __shared__ char smem[];
    const uint32_t sbase = smem_u32(smem);
    const int i = blockIdx.x;
    const int b = blockIdx.y;
    const int tid = threadIdx.x;
    const int wid = tid >> 5;
    const int lid = tid & 31;

    float*  sRed = (float*)(smem + OFF_RED);
    float2* sBW  = (float2*)(smem + OFF_BW);
    float*  sLf  = (float*)(smem + OFF_LF);
    float*  sEw  = (float*)(smem + OFF_EW);
    float*  sAgg = (float*)(smem + OFF_AGG);
    float*  sZa  = (float*)(smem + OFF_ZA);
    float*  sZb  = (float*)(smem + OFF_ZB);

    // Stage B tile (pre-swizzled) + left row + b2/W3 pairs
    {
        const uint4* src = (const uint4*)gB_img;
        uint4* dst = (uint4*)(smem + OFF_B);
#pragma unroll
        for (int t = tid; t < 4096; t += NTHREADS) dst[t] = src[t];
    }
    sLf[tid] = g_left[(b * NN + i) * HH + tid];
    if (tid < HH2) sBW[tid] = make_float2(b2[tid], W3[tid]);

    const float bias3 = b3[0];

    // A-build constants: thread covers k quad kq (k=4kq..4kq+3), j stride 4
    const int jp = tid >> 6;               // 0..3
    const int kq = tid & 63;               // 0..63
    __syncthreads();
    const float4 lfv = *(const float4*)&sLf[kq * 4];
    const uint32_t a_word_xorbase = (uint32_t)(kq >> 1) << 4;
    const uint32_t a_word_lo = (uint32_t)(kq & 1) << 3;

    // MMA addressing constants: warp = (wy 0..3 M-slot of 32, wx 0..1 N-slot of 64)
    const int wy = wid & 3;
    const int wx = wid >> 2;
    const int gid = lid >> 2, tig = lid & 3;
    const uint32_t hi16 = (uint32_t)lid >> 4;
    const int rowA0 = wy * 32 + (lid & 15);
    const uint32_t aRow0 = sbase + OFF_AH + rowA0 * 512;
    const uint32_t a_xor = (uint32_t)(rowA0 & 7) << 4;
    const int b_k = lid & 15;
    const uint32_t b_row0 = sbase + OFF_B + b_k * 256;
    const uint32_t b_xor = (uint32_t)(b_k & 7) << 4;

    // ---- 4 j-tiles of 128 ----
    for (int jt = 0; jt < 4; jt++) {
        const int j0 = jt * 128;
        const float* rbase = g_right + ((size_t)(b * NN + j0)) * HH;

        // Build A tile fp16 (+ combine previous tile's z partials)
#pragma unroll 4
        for (int it = 0; it < 32; it++) {
            int j = it * 4 + jp;
            float4 rv = *(const float4*)&rbase[j * HH + kq * 4];
            float v0 = fmaxf(lfv.x + rv.x, 0.f);
            float v1 = fmaxf(lfv.y + rv.y, 0.f);
            float v2 = fmaxf(lfv.z + rv.z, 0.f);
            float v3 = fmaxf(lfv.w + rv.w, 0.f);
            uint32_t w0 = pack_f16x2(v0, v1);
            uint32_t w1 = pack_f16x2(v2, v3);
            uint32_t off = (uint32_t)(j * 512) +
                           ((a_word_xorbase ^ ((uint32_t)(j & 7) << 4))) + a_word_lo;
            asm volatile("st.shared.v2.b32 [%0], {%1, %2};"
                         :: "r"(sbase + OFF_AH + off), "r"(w0), "r"(w1) : "memory");
        }
        if (jt && tid < 128) {
            float z = sZa[tid] + sZb[tid] + bias3;
            sEw[j0 - 128 + tid] = 1.f / (1.f + expf(-z));
        }
        __syncthreads();

        // ---- warp GEMM: D[32,64] = A[32,256] @ B[256,64] ----
        float acc[2][8][4];
#pragma unroll
        for (int mt = 0; mt < 2; mt++)
#pragma unroll
            for (int nt = 0; nt < 8; nt++)
#pragma unroll
                for (int c = 0; c < 4; c++) acc[mt][nt][c] = 0.f;

#pragma unroll 2
        for (int s = 0; s < 16; s++) {
            uint32_t a0[4], a1[4];
            uint32_t chunk = ((uint32_t)(2 * s + (int)hi16) << 4) ^ a_xor;
            ldsm_x4(a0, aRow0 + chunk);
            ldsm_x4(a1, aRow0 + 16 * 512 + chunk);
            uint32_t brow = b_row0 + (uint32_t)s * 4096;
#pragma unroll
            for (int np = 0; np < 4; np++) {
                uint32_t bb[4];
                uint32_t baddr = brow +
                    (((uint32_t)((wx << 3) + (np << 1) + (int)hi16) << 4) ^ b_xor);
                ldsm_x4_t(bb, baddr);
                mma16816(acc[0][np * 2],     a0, &bb[0]);
                mma16816(acc[0][np * 2 + 1], a0, &bb[2]);
                mma16816(acc[1][np * 2],     a1, &bb[0]);
                mma16816(acc[1][np * 2 + 1], a1, &bb[2]);
            }
        }

        // ---- epilogue: partial z over this warp's 64 cols ----
        float z00 = 0.f, z01 = 0.f, z10 = 0.f, z11 = 0.f;
#pragma unroll
        for (int nt = 0; nt < 8; nt++) {
            int c0 = wx * 64 + nt * 8 + tig * 2;
            float2 bw0 = sBW[c0];
            float2 bw1 = sBW[c0 + 1];
            z00 = fmaf(fmaxf(acc[0][nt][0] + bw0.x, 0.f), bw0.y, z00);
            z00 = fmaf(fmaxf(acc[0][nt][1] + bw1.x, 0.f), bw1.y, z00);
            z01 = fmaf(fmaxf(acc[0][nt][2] + bw0.x, 0.f), bw0.y, z01);
            z01 = fmaf(fmaxf(acc[0][nt][3] + bw1.x, 0.f), bw1.y, z01);
            z10 = fmaf(fmaxf(acc[1][nt][0] + bw0.x, 0.f), bw0.y, z10);
            z10 = fmaf(fmaxf(acc[1][nt][1] + bw1.x, 0.f), bw1.y, z10);
            z11 = fmaf(fmaxf(acc[1][nt][2] + bw0.x, 0.f), bw0.y, z11);
            z11 = fmaf(fmaxf(acc[1][nt][3] + bw1.x, 0.f), bw1.y, z11);
        }
        z00 += __shfl_xor_sync(0xffffffffu, z00, 1);
        z00 += __shfl_xor_sync(0xffffffffu, z00, 2);
        z01 += __shfl_xor_sync(0xffffffffu, z01, 1);
        z01 += __shfl_xor_sync(0xffffffffu, z01, 2);
        z10 += __shfl_xor_sync(0xffffffffu, z10, 1);
        z10 += __shfl_xor_sync(0xffffffffu, z10, 2);
        z11 += __shfl_xor_sync(0xffffffffu, z11, 1);
        z11 += __shfl_xor_sync(0xffffffffu, z11, 2);
        if (tig == 0) {
            float* zdst = wx ? sZb : sZa;
            int rb = wy * 32 + gid;
            zdst[rb]          = z00;
            zdst[rb + 8]      = z01;
            zdst[rb + 16]     = z10;
            zdst[rb + 24]     = z11;
        }
        __syncthreads();
    }
    // combine last tile
    if (tid < 128) {
        float z = sZa[tid] + sZb[tid] + bias3;
        sEw[384 + tid] = 1.f / (1.f + expf(-z));
    }
    __syncthreads();

    // ---- softmax over j of base_adj*ew + I ----
    float v0, v1;
    {
        const float* ba = base_adj + ((size_t)(b * NN + i)) * NN;
        int ja = tid, jb = tid + 256;
        v0 = ba[ja] * sEw[ja] + (ja == i ? 1.f : 0.f);
        v1 = ba[jb] * sEw[jb] + (jb == i ? 1.f : 0.f);
    }
    float m = fmaxf(v0, v1);
#pragma unroll
    for (int off = 16; off > 0; off >>= 1)
        m = fmaxf(m, __shfl_xor_sync(0xffffffffu, m, off));
    if (lid == 0) sRed[wid] = m;
    __syncthreads();
    if (tid == 0) {
        float mm = sRed[0];
#pragma unroll
        for (int w = 1; w < 8; w++) mm = fmaxf(mm, sRed[w]);
        sRed[0] = mm;
    }
    __syncthreads();
    m = sRed[0];
    __syncthreads();

    float e0 = expf(v0 - m);
    float e1 = expf(v1 - m);
    float s = e0 + e1;
#pragma unroll
    for (int off = 16; off > 0; off >>= 1)
        s += __shfl_xor_sync(0xffffffffu, s, off);
    if (lid == 0) sRed[wid] = s;
    __syncthreads();
    if (tid == 0) {
        float ss = 0.f;
#pragma unroll
        for (int w = 0; w < 8; w++) ss += sRed[w];
        sRed[0] = ss;
    }
    __syncthreads();
    const float inv = 1.f / sRed[0];
    sEw[tid] = e0 * inv;
    sEw[tid + 256] = e1 * inv;
    __syncthreads();

    // ---- agg[d] = sum_j p[j] * x[b,j,d] (unroll 8 for MLP) ----
    {
        const float* xb = x + (size_t)b * NN * DD;
        float a0 = 0.f, a1 = 0.f, a2 = 0.f, a3 = 0.f;
        float a4 = 0.f, a5 = 0.f, a6 = 0.f, a7 = 0.f;
#pragma unroll 2
        for (int j = 0; j < NN; j += 8) {
            a0 = fmaf(sEw[j],     xb[(j)     * DD + tid], a0);
            a1 = fmaf(sEw[j + 1], xb[(j + 1) * DD + tid], a1);
            a2 = fmaf(sEw[j + 2], xb[(j + 2) * DD + tid], a2);
            a3 = fmaf(sEw[j + 3], xb[(j + 3) * DD + tid], a3);
            a4 = fmaf(sEw[j + 4], xb[(j + 4) * DD + tid], a4);
            a5 = fmaf(sEw[j + 5], xb[(j + 5) * DD + tid], a5);
            a6 = fmaf(sEw[j + 6], xb[(j + 6) * DD + tid], a6);
            a7 = fmaf(sEw[j + 7], xb[(j + 7) * DD + tid], a7);
        }
        sAgg[tid] = ((a0 + a1) + (a2 + a3)) + ((a4 + a5) + (a6 + a7));
    }
    __syncthreads();

    // ---- out[h] = sum_d agg[d]*Wg[d,h] + bg[h] (unroll 8) ----
    {
        float o0 = bg[tid], o1 = 0.f, o2 = 0.f, o3 = 0.f;
        float o4 = 0.f, o5 = 0.f, o6 = 0.f, o7 = 0.f;
#pragma unroll 2
        for (int d = 0; d < DD; d += 8) {
            o0 = fmaf(sAgg[d],     Wg[(d)     * HH + tid], o0);
            o1 = fmaf(sAgg[d + 1], Wg[(d + 1) * HH + tid], o1);
            o2 = fmaf(sAgg[d + 2], Wg[(d + 2) * HH + tid], o2);
            o3 = fmaf(sAgg[d + 3], Wg[(d + 3) * HH + tid], o3);
            o4 = fmaf(sAgg[d + 4], Wg[(d + 4) * HH + tid], o4);
            o5 = fmaf(sAgg[d + 5], Wg[(d + 5) * HH + tid], o5);
            o6 = fmaf(sAgg[d + 6], Wg[(d + 6) * HH + tid], o6);
            o7 = fmaf(sAgg[d + 7], Wg[(d + 7) * HH + tid], o7);
        }
        out[((size_t)(b * NN + i)) * HH + tid] =
            ((o0 + o1) + (o2 + o3)) + ((o4 + o5) + (o6 + o7));
    }
}

// ---------------------------------------------------------------------------
extern "C" void kernel_launch(void* const* d_in, const int* in_sizes, int n_in,
                              void* d_out, int out_size)
{
    const float* x        = (const float*)d_in[0];
    const float* base_adj = (const float*)d_in[1];
    const float* W1       = (const float*)d_in[2];
    const float* b1       = (const float*)d_in[3];
    const float* W2       = (const float*)d_in[4];
    const float* b2       = (const float*)d_in[5];
    const float* W3       = (const float*)d_in[6];
    const float* b3       = (const float*)d_in[7];
    const float* Wg       = (const float*)d_in[8];
    const float* bg       = (const float*)d_in[9];
    float* out = (float*)d_out;

    cudaFuncSetAttribute(main_kernel,
                         cudaFuncAttributeMaxDynamicSharedMemorySize,
                         SMEM_TOTAL);

    bprep_kernel<<<64, 256>>>(W2);
    lr_kernel<<<BB * NN / LR_ROWS, 256>>>(x, W1, b1);
    main_kernel<<<dim3(NN, BB), NTHREADS, SMEM_TOTAL>>>(
        x, base_adj, b2, W3, b3, Wg, bg, out);
}

// round 5
// speedup vs baseline: 6.1824x; 1.0709x over previous
#include <cuda_runtime.h>
#include <cuda_fp16.h>
#include <math.h>
#include <stdint.h>

#define BB 2
#define NN 512
#define DD 256
#define HH 256
#define HH2 128
#define NTHREADS 256

// SMEM byte offsets
#define OFF_RED   64
#define OFF_BW    256      // float2[128]: {b2[c], W3[c]}
#define OFF_LF    1280     // float[512]: left rows i0,i1
#define OFF_EW    3328     // float[1024]: edge weights / probs (2 rows)
#define OFF_AGG   7424     // float[512]
#define OFF_B     12288    // 64KB: W2 fp16 [k=256][64 words] swizzled
#define OFF_A     77824    // 128KB: A tile fp16 [256 rows][128 words] swizzled
#define SMEM_TOTAL 208896

// Scratch (__device__ globals: allocation-free rule)
__device__ float    g_left[BB * NN * HH];
__device__ __half   g_right_h[BB * NN * HH];
__device__ uint32_t gB_img[16384];   // 64KB swizzled W2 fp16 image

// ---------------------------------------------------------------------------
// helpers
// ---------------------------------------------------------------------------
__device__ __forceinline__ uint32_t smem_u32(const void* p) {
    uint32_t a;
    asm("{ .reg .u64 t; cvta.to.shared.u64 t, %1; cvt.u32.u64 %0, t; }"
        : "=r"(a) : "l"(p));
    return a;
}
__device__ __forceinline__ uint32_t pack_f16x2(float lo, float hi) {
    uint32_t r;
    asm("cvt.rn.f16x2.f32 %0, %1, %2;" : "=r"(r) : "f"(hi), "f"(lo));
    return r;
}
__device__ __forceinline__ void ldsm_x4(uint32_t* r, uint32_t addr) {
    asm volatile("ldmatrix.sync.aligned.m8n8.x4.shared.b16 {%0,%1,%2,%3}, [%4];"
                 : "=r"(r[0]), "=r"(r[1]), "=r"(r[2]), "=r"(r[3]) : "r"(addr));
}
__device__ __forceinline__ void ldsm_x4_t(uint32_t* r, uint32_t addr) {
    asm volatile("ldmatrix.sync.aligned.m8n8.x4.trans.shared.b16 {%0,%1,%2,%3}, [%4];"
                 : "=r"(r[0]), "=r"(r[1]), "=r"(r[2]), "=r"(r[3]) : "r"(addr));
}
__device__ __forceinline__ void mma16816(float* d, const uint32_t* a,
                                         const uint32_t* b) {
    asm volatile(
        "mma.sync.aligned.m16n8k16.row.col.f32.f16.f16.f32 "
        "{%0,%1,%2,%3}, {%4,%5,%6,%7}, {%8,%9}, {%0,%1,%2,%3};"
        : "+f"(d[0]), "+f"(d[1]), "+f"(d[2]), "+f"(d[3])
        : "r"(a[0]), "r"(a[1]), "r"(a[2]), "r"(a[3]), "r"(b[0]), "r"(b[1]));
}

// ---------------------------------------------------------------------------
// Kernel A: left/right projections; right stored fp16
// ---------------------------------------------------------------------------
#define LR_ROWS 8
__global__ __launch_bounds__(256) void lr_kernel(
    const float* __restrict__ x, const float* __restrict__ W1,
    const float* __restrict__ b1)
{
    __shared__ float sx[LR_ROWS][DD];
    const int r0 = blockIdx.x * LR_ROWS;
    const int h = threadIdx.x;
#pragma unroll
    for (int t = 0; t < LR_ROWS; t++)
        sx[t][h] = x[(r0 + t) * DD + h];
    __syncthreads();

    float l[LR_ROWS], r[LR_ROWS];
#pragma unroll
    for (int t = 0; t < LR_ROWS; t++) { l[t] = b1[h]; r[t] = 0.f; }

#pragma unroll 2
    for (int d = 0; d < DD; d += 4) {
        float wl[4], wr[4];
#pragma unroll
        for (int q = 0; q < 4; q++) {
            wl[q] = W1[(d + q) * HH + h];
            wr[q] = W1[(DD + d + q) * HH + h];
        }
#pragma unroll
        for (int t = 0; t < LR_ROWS; t++) {
            float4 xv = *(const float4*)&sx[t][d];
            l[t] = fmaf(xv.x, wl[0], l[t]); r[t] = fmaf(xv.x, wr[0], r[t]);
            l[t] = fmaf(xv.y, wl[1], l[t]); r[t] = fmaf(xv.y, wr[1], r[t]);
            l[t] = fmaf(xv.z, wl[2], l[t]); r[t] = fmaf(xv.z, wr[2], r[t]);
            l[t] = fmaf(xv.w, wl[3], l[t]); r[t] = fmaf(xv.w, wr[3], r[t]);
        }
    }
#pragma unroll
    for (int t = 0; t < LR_ROWS; t++) {
        g_left[(r0 + t) * HH + h] = l[t];
        g_right_h[(r0 + t) * HH + h] = __float2half(r[t]);
    }
}

// ---------------------------------------------------------------------------
// Kernel P: swizzled fp16 image of W2 [k=256 rows][64 words of n]
// ---------------------------------------------------------------------------
__global__ __launch_bounds__(256) void bprep_kernel(const float* __restrict__ W2)
{
    int idx = blockIdx.x * 256 + threadIdx.x;
    int k = idx >> 6;
    int w = idx & 63;
    float2 v = ((const float2*)W2)[k * 64 + w];
    uint32_t packed = pack_f16x2(v.x, v.y);
    uint32_t off = (uint32_t)(k * 256 + ((((w >> 2) ^ (k & 7)) << 4)) + (w & 3) * 4);
    gB_img[off >> 2] = packed;
}

// ---------------------------------------------------------------------------
// Kernel B: per (b, i-pair) — fp16 mma pair-MLP for 2 query rows + edge dot +
// sigmoid + softmax + p@x + @Wg + bg
// ---------------------------------------------------------------------------
__global__ __launch_bounds__(NTHREADS, 1)
void main_kernel(
    const float* __restrict__ x, const float* __restrict__ base_adj,
    const float* __restrict__ b2, const float* __restrict__ W3,
    const float* __restrict__ b3, const float* __restrict__ Wg,
    const float* __restrict__ bg, float* __restrict__ out)
{
    extern __shared__ char smem[];
    const uint32_t sbase = smem_u32(smem);
    const int i0 = blockIdx.x * 2;
    const int b = blockIdx.y;
    const int tid = threadIdx.x;
    const int wid = tid >> 5;
    const int lid = tid & 31;

    float*  sRed = (float*)(smem + OFF_RED);
    float2* sBW  = (float2*)(smem + OFF_BW);
    float*  sLf  = (float*)(smem + OFF_LF);
    float*  sEw  = (float*)(smem + OFF_EW);
    float*  sAgg = (float*)(smem + OFF_AGG);

    // Stage B tile (pre-swizzled) + left rows + b2/W3 pairs
    {
        const uint4* src = (const uint4*)gB_img;
        uint4* dst = (uint4*)(smem + OFF_B);
#pragma unroll
        for (int t = tid; t < 4096; t += NTHREADS) dst[t] = src[t];
    }
    sLf[tid]       = g_left[((size_t)(b * NN + i0)) * HH + tid];
    sLf[256 + tid] = g_left[((size_t)(b * NN + i0 + 1)) * HH + tid];
    if (tid < HH2) sBW[tid] = make_float2(b2[tid], W3[tid]);

    const float bias3 = b3[0];

    // A-build constants: thread covers k quad kq, j stride 4
    const int jp = tid >> 6;               // 0..3
    const int kq = tid & 63;               // 0..63
    __syncthreads();
    const float4 lfv0 = *(const float4*)&sLf[kq * 4];
    const float4 lfv1 = *(const float4*)&sLf[256 + kq * 4];
    const uint32_t a_word_xorbase = (uint32_t)(kq >> 1) << 4;
    const uint32_t a_word_lo = (uint32_t)(kq & 1) << 3;

    // MMA addressing: warp wy=wid owns stacked rows wy*32..+31, all 128 cols
    const int gid = lid >> 2, tig = lid & 3;
    const uint32_t hi16 = (uint32_t)lid >> 4;
    const int rowA0 = wid * 32 + (lid & 15);
    const uint32_t aRow0 = sbase + OFF_A + rowA0 * 512;
    const uint32_t a_xor = (uint32_t)(rowA0 & 7) << 4;
    const int b_k = lid & 15;
    const uint32_t b_row0 = sbase + OFF_B + b_k * 256;
    const uint32_t b_xor = (uint32_t)(b_k & 7) << 4;

    // ---- 4 j-tiles of 128 ----
    for (int jt = 0; jt < 4; jt++) {
        const int j0 = jt * 128;
        const __half* rbase = g_right_h + ((size_t)(b * NN + j0)) * HH;

        // Build stacked A tile: rows 0..127 = i0, 128..255 = i1
#pragma unroll 4
        for (int it = 0; it < 32; it++) {
            int j = it * 4 + jp;
            uint2 u = *(const uint2*)&rbase[j * HH + kq * 4];
            float2 f0 = __half22float2(*(__half2*)&u.x);
            float2 f1 = __half22float2(*(__half2*)&u.y);
            uint32_t w0 = pack_f16x2(fmaxf(lfv0.x + f0.x, 0.f), fmaxf(lfv0.y + f0.y, 0.f));
            uint32_t w1 = pack_f16x2(fmaxf(lfv0.z + f1.x, 0.f), fmaxf(lfv0.w + f1.y, 0.f));
            uint32_t off = (uint32_t)(j * 512) +
                           (a_word_xorbase ^ ((uint32_t)(j & 7) << 4)) + a_word_lo;
            asm volatile("st.shared.v2.b32 [%0], {%1, %2};"
                         :: "r"(sbase + OFF_A + off), "r"(w0), "r"(w1) : "memory");
            int j2 = j + 128;
            uint32_t w2 = pack_f16x2(fmaxf(lfv1.x + f0.x, 0.f), fmaxf(lfv1.y + f0.y, 0.f));
            uint32_t w3p = pack_f16x2(fmaxf(lfv1.z + f1.x, 0.f), fmaxf(lfv1.w + f1.y, 0.f));
            uint32_t off2 = (uint32_t)(j2 * 512) +
                            (a_word_xorbase ^ ((uint32_t)(j2 & 7) << 4)) + a_word_lo;
            asm volatile("st.shared.v2.b32 [%0], {%1, %2};"
                         :: "r"(sbase + OFF_A + off2), "r"(w2), "r"(w3p) : "memory");
        }
        __syncthreads();

        // ---- warp GEMM: D[32,128] = A[32,256] @ B[256,128] ----
        float acc[2][16][4];
#pragma unroll
        for (int mt = 0; mt < 2; mt++)
#pragma unroll
            for (int nt = 0; nt < 16; nt++)
#pragma unroll
                for (int c = 0; c < 4; c++) acc[mt][nt][c] = 0.f;

#pragma unroll 1
        for (int s = 0; s < 16; s++) {
            uint32_t a0[4], a1[4];
            uint32_t chunk = ((uint32_t)(2 * s + (int)hi16) << 4) ^ a_xor;
            ldsm_x4(a0, aRow0 + chunk);
            ldsm_x4(a1, aRow0 + 16 * 512 + chunk);
            uint32_t brow = b_row0 + (uint32_t)s * 4096;
#pragma unroll
            for (int np = 0; np < 8; np++) {
                uint32_t bb[4];
                uint32_t baddr = brow +
                    (((uint32_t)((np << 1) + (int)hi16) << 4) ^ b_xor);
                ldsm_x4_t(bb, baddr);
                mma16816(acc[0][np * 2],     a0, &bb[0]);
                mma16816(acc[0][np * 2 + 1], a0, &bb[2]);
                mma16816(acc[1][np * 2],     a1, &bb[0]);
                mma16816(acc[1][np * 2 + 1], a1, &bb[2]);
            }
        }

        // ---- epilogue: full z per row (warp owns all 128 cols) ----
#pragma unroll
        for (int mt = 0; mt < 2; mt++) {
            float z0 = 0.f, z1 = 0.f;
#pragma unroll
            for (int nt = 0; nt < 16; nt++) {
                int c0 = nt * 8 + tig * 2;
                float2 bw0 = sBW[c0];
                float2 bw1 = sBW[c0 + 1];
                z0 = fmaf(fmaxf(acc[mt][nt][0] + bw0.x, 0.f), bw0.y, z0);
                z0 = fmaf(fmaxf(acc[mt][nt][1] + bw1.x, 0.f), bw1.y, z0);
                z1 = fmaf(fmaxf(acc[mt][nt][2] + bw0.x, 0.f), bw0.y, z1);
                z1 = fmaf(fmaxf(acc[mt][nt][3] + bw1.x, 0.f), bw1.y, z1);
            }
            z0 += __shfl_xor_sync(0xffffffffu, z0, 1);
            z0 += __shfl_xor_sync(0xffffffffu, z0, 2);
            z1 += __shfl_xor_sync(0xffffffffu, z1, 1);
            z1 += __shfl_xor_sync(0xffffffffu, z1, 2);
            if (tig == 0) {
                int r = wid * 32 + mt * 16 + gid;        // stacked row
                int isel = r >> 7;
                int jj = j0 + (r & 127);
                sEw[isel * 512 + jj] =
                    1.f / (1.f + expf(-(z0 + bias3)));
                int r2 = r + 8;
                int isel2 = r2 >> 7;
                sEw[isel2 * 512 + j0 + (r2 & 127)] =
                    1.f / (1.f + expf(-(z1 + bias3)));
            }
        }
        __syncthreads();
    }

    // ---- softmax per query row g ----
#pragma unroll
    for (int g = 0; g < 2; g++) {
        const int ii = i0 + g;
        const float* ba = base_adj + ((size_t)(b * NN + ii)) * NN;
        float* ew = sEw + g * 512;
        int ja = tid, jb = tid + 256;
        float v0 = ba[ja] * ew[ja] + (ja == ii ? 1.f : 0.f);
        float v1 = ba[jb] * ew[jb] + (jb == ii ? 1.f : 0.f);

        float m = fmaxf(v0, v1);
#pragma unroll
        for (int off = 16; off > 0; off >>= 1)
            m = fmaxf(m, __shfl_xor_sync(0xffffffffu, m, off));
        if (lid == 0) sRed[wid] = m;
        __syncthreads();
        if (tid == 0) {
            float mm = sRed[0];
#pragma unroll
            for (int w = 1; w < 8; w++) mm = fmaxf(mm, sRed[w]);
            sRed[0] = mm;
        }
        __syncthreads();
        m = sRed[0];
        __syncthreads();

        float e0 = expf(v0 - m);
        float e1 = expf(v1 - m);
        float s = e0 + e1;
#pragma unroll
        for (int off = 16; off > 0; off >>= 1)
            s += __shfl_xor_sync(0xffffffffu, s, off);
        if (lid == 0) sRed[wid] = s;
        __syncthreads();
        if (tid == 0) {
            float ss = 0.f;
#pragma unroll
            for (int w = 0; w < 8; w++) ss += sRed[w];
            sRed[0] = ss;
        }
        __syncthreads();
        const float inv = 1.f / sRed[0];
        ew[ja] = e0 * inv;
        ew[jb] = e1 * inv;
        __syncthreads();
    }

    // ---- agg: both query rows share each x load ----
    {
        const float* xb = x + (size_t)b * NN * DD;
        float a00 = 0.f, a01 = 0.f, a02 = 0.f, a03 = 0.f;
        float a10 = 0.f, a11 = 0.f, a12 = 0.f, a13 = 0.f;
#pragma unroll 2
        for (int j = 0; j < NN; j += 4) {
            float x0 = xb[(j)     * DD + tid];
            float x1 = xb[(j + 1) * DD + tid];
            float x2 = xb[(j + 2) * DD + tid];
            float x3 = xb[(j + 3) * DD + tid];
            a00 = fmaf(sEw[j],           x0, a00);
            a01 = fmaf(sEw[j + 1],       x1, a01);
            a02 = fmaf(sEw[j + 2],       x2, a02);
            a03 = fmaf(sEw[j + 3],       x3, a03);
            a10 = fmaf(sEw[512 + j],     x0, a10);
            a11 = fmaf(sEw[512 + j + 1], x1, a11);
            a12 = fmaf(sEw[512 + j + 2], x2, a12);
            a13 = fmaf(sEw[512 + j + 3], x3, a13);
        }
        sAgg[tid]       = (a00 + a01) + (a02 + a03);
        sAgg[256 + tid] = (a10 + a11) + (a12 + a13);
    }
    __syncthreads();

    // ---- out rows i0,i1 share each Wg load ----
    {
        float o00 = bg[tid], o01 = 0.f, o02 = 0.f, o03 = 0.f;
        float o10 = bg[tid], o11 = 0.f, o12 = 0.f, o13 = 0.f;
#pragma unroll 2
        for (int d = 0; d < DD; d += 4) {
            float w0 = Wg[(d)     * HH + tid];
            float w1 = Wg[(d + 1) * HH + tid];
            float w2 = Wg[(d + 2) * HH + tid];
            float w3v = Wg[(d + 3) * HH + tid];
            o00 = fmaf(sAgg[d],           w0, o00);
            o01 = fmaf(sAgg[d + 1],       w1, o01);
            o02 = fmaf(sAgg[d + 2],       w2, o02);
            o03 = fmaf(sAgg[d + 3],       w3v, o03);
            o10 = fmaf(sAgg[256 + d],     w0, o10);
            o11 = fmaf(sAgg[256 + d + 1], w1, o11);
            o12 = fmaf(sAgg[256 + d + 2], w2, o12);
            o13 = fmaf(sAgg[256 + d + 3], w3v, o13);
        }
        out[((size_t)(b * NN + i0)) * HH + tid]     = (o00 + o01) + (o02 + o03);
        out[((size_t)(b * NN + i0 + 1)) * HH + tid] = (o10 + o11) + (o12 + o13);
    }
}

// ---------------------------------------------------------------------------
extern "C" void kernel_launch(void* const* d_in, const int* in_sizes, int n_in,
                              void* d_out, int out_size)
{
    const float* x        = (const float*)d_in[0];
    const float* base_adj = (const float*)d_in[1];
    const float* W1       = (const float*)d_in[2];
    const float* b1       = (const float*)d_in[3];
    const float* W2       = (const float*)d_in[4];
    const float* b2       = (const float*)d_in[5];
    const float* W3       = (const float*)d_in[6];
    const float* b3       = (const float*)d_in[7];
    const float* Wg       = (const float*)d_in[8];
    const float* bg       = (const float*)d_in[9];
    float* out = (float*)d_out;

    cudaFuncSetAttribute(main_kernel,
                         cudaFuncAttributeMaxDynamicSharedMemorySize,
                         SMEM_TOTAL);

    bprep_kernel<<<64, 256>>>(W2);
    lr_kernel<<<BB * NN / LR_ROWS, 256>>>(x, W1, b1);
    main_kernel<<<dim3(NN / 2, BB), NTHREADS, SMEM_TOTAL>>>(
        x, base_adj, b2, W3, b3, Wg, bg, out);
}

// round 7
// speedup vs baseline: 8.3293x; 1.3473x over previous
#include <cuda_runtime.h>
#include <cuda_fp16.h>
#include <math.h>
#include <stdint.h>

#define BB 2
#define NN 512
#define DD 256
#define HH 256
#define HH2 128
#define NTHREADS 256

// SMEM byte offsets
#define OFF_RED   64
#define OFF_BW    256      // float2[128]: {b2[c], W3[c]}
#define OFF_LF    1280     // float[512]: left rows i0,i1
#define OFF_EW    3328     // float[1024]: edge weights / probs (2 rows)
#define OFF_AGG   7424     // float[512]
#define OFF_ZP    9472     // float[64][4]: partial z per (stacked row, N-warp)
#define OFF_B     12288    // 64KB: W2 fp16 [k=256][64 words] swizzled
#define OFF_A     77824    // 32KB: A tile fp16 [64 rows][128 words] swizzled
#define SMEM_TOTAL 110592

// Scratch (__device__ globals: allocation-free rule)
__device__ float    g_left[BB * NN * HH];
__device__ __half   g_right_h[BB * NN * HH];
__device__ __half   g_x_h[BB * NN * DD];
__device__ uint32_t gB_img[16384];   // 64KB swizzled W2 fp16 image

// ---------------------------------------------------------------------------
// helpers
// ---------------------------------------------------------------------------
__device__ __forceinline__ uint32_t smem_u32(const void* p) {
    uint32_t a;
    asm("{ .reg .u64 t; cvta.to.shared.u64 t, %1; cvt.u32.u64 %0, t; }"
        : "=r"(a) : "l"(p));
    return a;
}
__device__ __forceinline__ uint32_t pack_f16x2(float lo, float hi) {
    uint32_t r;
    asm("cvt.rn.f16x2.f32 %0, %1, %2;" : "=r"(r) : "f"(hi), "f"(lo));
    return r;
}
__device__ __forceinline__ void ldsm_x4(uint32_t* r, uint32_t addr) {
    asm volatile("ldmatrix.sync.aligned.m8n8.x4.shared.b16 {%0,%1,%2,%3}, [%4];"
                 : "=r"(r[0]), "=r"(r[1]), "=r"(r[2]), "=r"(r[3]) : "r"(addr));
}
__device__ __forceinline__ void ldsm_x4_t(uint32_t* r, uint32_t addr) {
    asm volatile("ldmatrix.sync.aligned.m8n8.x4.trans.shared.b16 {%0,%1,%2,%3}, [%4];"
                 : "=r"(r[0]), "=r"(r[1]), "=r"(r[2]), "=r"(r[3]) : "r"(addr));
}
__device__ __forceinline__ void mma16816(float* d, const uint32_t* a,
                                         const uint32_t* b) {
    asm volatile(
        "mma.sync.aligned.m16n8k16.row.col.f32.f16.f16.f32 "
        "{%0,%1,%2,%3}, {%4,%5,%6,%7}, {%8,%9}, {%0,%1,%2,%3};"
        : "+f"(d[0]), "+f"(d[1]), "+f"(d[2]), "+f"(d[3])
        : "r"(a[0]), "r"(a[1]), "r"(a[2]), "r"(a[3]), "r"(b[0]), "r"(b[1]));
}

// ---------------------------------------------------------------------------
// Kernel A: left/right projections; right + x stored fp16
// ---------------------------------------------------------------------------
#define LR_ROWS 8
__global__ __launch_bounds__(256) void lr_kernel(
    const float* __restrict__ x, const float* __restrict__ W1,
    const float* __restrict__ b1)
{
    __shared__ float sx[LR_ROWS][DD];
    const int r0 = blockIdx.x * LR_ROWS;
    const int h = threadIdx.x;
#pragma unroll
    for (int t = 0; t < LR_ROWS; t++) {
        float xv = x[(r0 + t) * DD + h];
        sx[t][h] = xv;
        g_x_h[(r0 + t) * DD + h] = __float2half(xv);
    }
    __syncthreads();

    float l[LR_ROWS], r[LR_ROWS];
#pragma unroll
    for (int t = 0; t < LR_ROWS; t++) { l[t] = b1[h]; r[t] = 0.f; }

#pragma unroll 2
    for (int d = 0; d < DD; d += 4) {
        float wl[4], wr[4];
#pragma unroll
        for (int q = 0; q < 4; q++) {
            wl[q] = W1[(d + q) * HH + h];
            wr[q] = W1[(DD + d + q) * HH + h];
        }
#pragma unroll
        for (int t = 0; t < LR_ROWS; t++) {
            float4 xv = *(const float4*)&sx[t][d];
            l[t] = fmaf(xv.x, wl[0], l[t]); r[t] = fmaf(xv.x, wr[0], r[t]);
            l[t] = fmaf(xv.y, wl[1], l[t]); r[t] = fmaf(xv.y, wr[1], r[t]);
            l[t] = fmaf(xv.z, wl[2], l[t]); r[t] = fmaf(xv.z, wr[2], r[t]);
            l[t] = fmaf(xv.w, wl[3], l[t]); r[t] = fmaf(xv.w, wr[3], r[t]);
        }
    }
#pragma unroll
    for (int t = 0; t < LR_ROWS; t++) {
        g_left[(r0 + t) * HH + h] = l[t];
        g_right_h[(r0 + t) * HH + h] = __float2half(r[t]);
    }
}

// ---------------------------------------------------------------------------
// Kernel P: swizzled fp16 image of W2 [k=256 rows][64 words of n]
// ---------------------------------------------------------------------------
__global__ __launch_bounds__(256) void bprep_kernel(const float* __restrict__ W2)
{
    int idx = blockIdx.x * 256 + threadIdx.x;
    int k = idx >> 6;
    int w = idx & 63;
    float2 v = ((const float2*)W2)[k * 64 + w];
    uint32_t packed = pack_f16x2(v.x, v.y);
    uint32_t off = (uint32_t)(k * 256 + ((((w >> 2) ^ (k & 7)) << 4)) + (w & 3) * 4);
    gB_img[off >> 2] = packed;
}

// ---------------------------------------------------------------------------
// Kernel B: per (b, i-pair) — fp16 mma pair-MLP, j-tile 32, 2 CTAs/SM
// ---------------------------------------------------------------------------
__global__ __launch_bounds__(NTHREADS, 2)
void main_kernel(
    const float* __restrict__ base_adj,
    const float* __restrict__ b2, const float* __restrict__ W3,
    const float* __restrict__ b3, const float* __restrict__ Wg,
    const float* __restrict__ bg, float* __restrict__ out)
{
    extern __shared__ char smem[];
    const uint32_t sbase = smem_u32(smem);
    const int i0 = blockIdx.x * 2;
    const int b = blockIdx.y;
    const int tid = threadIdx.x;
    const int wid = tid >> 5;
    const int lid = tid & 31;

    float*  sRed = (float*)(smem + OFF_RED);
    float2* sBW  = (float2*)(smem + OFF_BW);
    float*  sLf  = (float*)(smem + OFF_LF);
    float*  sEw  = (float*)(smem + OFF_EW);
    float*  sAgg = (float*)(smem + OFF_AGG);
    float*  sZp  = (float*)(smem + OFF_ZP);

    // Stage B tile (pre-swizzled) + left rows + b2/W3 pairs
    {
        const uint4* src = (const uint4*)gB_img;
        uint4* dst = (uint4*)(smem + OFF_B);
#pragma unroll
        for (int t = tid; t < 4096; t += NTHREADS) dst[t] = src[t];
    }
    sLf[tid]       = g_left[((size_t)(b * NN + i0)) * HH + tid];
    sLf[256 + tid] = g_left[((size_t)(b * NN + i0 + 1)) * HH + tid];
    if (tid < HH2) sBW[tid] = make_float2(b2[tid], W3[tid]);

    const float bias3 = b3[0];

    // A-build constants: thread covers k quad kq, j stride 4
    const int jp = tid >> 6;               // 0..3
    const int kq = tid & 63;               // 0..63
    __syncthreads();
    const float4 lfv0 = *(const float4*)&sLf[kq * 4];
    const float4 lfv1 = *(const float4*)&sLf[256 + kq * 4];
    const uint32_t a_word_xorbase = (uint32_t)(kq >> 1) << 4;
    const uint32_t a_word_lo = (uint32_t)(kq & 1) << 3;

    // MMA addressing: warp = (wy 0..1 stacked-M half of 32, wx 0..3 N-slot of 32)
    const int wy = wid & 1;
    const int wx = wid >> 1;
    const int gid = lid >> 2, tig = lid & 3;
    const uint32_t hi16 = (uint32_t)lid >> 4;
    const int rowA0 = wy * 32 + (lid & 15);
    const uint32_t aRow0 = sbase + OFF_A + rowA0 * 512;
    const uint32_t a_xor = (uint32_t)(rowA0 & 7) << 4;
    const int b_k = lid & 15;
    const uint32_t b_row0 = sbase + OFF_B + b_k * 256;
    const uint32_t b_xor = (uint32_t)(b_k & 7) << 4;
    const uint32_t bsel0 = ((uint32_t)((wx * 2) * 2 + (int)hi16) << 4) ^ b_xor;
    const uint32_t bsel1 = ((uint32_t)((wx * 2 + 1) * 2 + (int)hi16) << 4) ^ b_xor;

    // ---- 16 j-tiles of 32 ----
    for (int jt = 0; jt < 16; jt++) {
        const int j0 = jt * 32;
        const __half* rbase = g_right_h + ((size_t)(b * NN + j0)) * HH;

        // Combine previous tile's z partials
        if (jt && tid < 64) {
            float z = sZp[tid * 4] + sZp[tid * 4 + 1] + sZp[tid * 4 + 2] +
                      sZp[tid * 4 + 3] + bias3;
            int isel = tid >> 5;
            sEw[isel * 512 + j0 - 32 + (tid & 31)] = 1.f / (1.f + expf(-z));
        }

        // Build stacked A tile: rows 0..31 = i0, rows 32..63 = i1
#pragma unroll
        for (int it = 0; it < 8; it++) {
            int j = it * 4 + jp;
            uint2 u = *(const uint2*)&rbase[j * HH + kq * 4];
            float2 f0 = __half22float2(*(__half2*)&u.x);
            float2 f1 = __half22float2(*(__half2*)&u.y);
            uint32_t w0 = pack_f16x2(fmaxf(lfv0.x + f0.x, 0.f), fmaxf(lfv0.y + f0.y, 0.f));
            uint32_t w1 = pack_f16x2(fmaxf(lfv0.z + f1.x, 0.f), fmaxf(lfv0.w + f1.y, 0.f));
            uint32_t off = (uint32_t)(j * 512) +
                           (a_word_xorbase ^ ((uint32_t)(j & 7) << 4)) + a_word_lo;
            asm volatile("st.shared.v2.b32 [%0], {%1, %2};"
                         :: "r"(sbase + OFF_A + off), "r"(w0), "r"(w1) : "memory");
            int j2 = j + 32;
            uint32_t w2 = pack_f16x2(fmaxf(lfv1.x + f0.x, 0.f), fmaxf(lfv1.y + f0.y, 0.f));
            uint32_t w3p = pack_f16x2(fmaxf(lfv1.z + f1.x, 0.f), fmaxf(lfv1.w + f1.y, 0.f));
            uint32_t off2 = (uint32_t)(j2 * 512) +
                            (a_word_xorbase ^ ((uint32_t)(j2 & 7) << 4)) + a_word_lo;
            asm volatile("st.shared.v2.b32 [%0], {%1, %2};"
                         :: "r"(sbase + OFF_A + off2), "r"(w2), "r"(w3p) : "memory");
        }
        __syncthreads();

        // ---- warp GEMM: D[32,32] = A(rows wy*32..+31)[32,256] @ B[256,32] ----
        // a0 covers rows wy*32+0..15, a1 covers rows wy*32+16..31 (+16*512 B)
        float acc[2][4][4];
#pragma unroll
        for (int mt = 0; mt < 2; mt++)
#pragma unroll
            for (int g = 0; g < 4; g++)
#pragma unroll
                for (int c = 0; c < 4; c++) acc[mt][g][c] = 0.f;

#pragma unroll 4
        for (int s = 0; s < 16; s++) {
            uint32_t a0[4], a1[4], bb0[4], bb1[4];
            uint32_t chunk = ((uint32_t)(2 * s + (int)hi16) << 4) ^ a_xor;
            ldsm_x4(a0, aRow0 + chunk);
            ldsm_x4(a1, aRow0 + 16 * 512 + chunk);
            uint32_t brow = b_row0 + (uint32_t)s * 4096;
            ldsm_x4_t(bb0, brow + bsel0);
            ldsm_x4_t(bb1, brow + bsel1);
            mma16816(acc[0][0], a0, &bb0[0]);
            mma16816(acc[0][1], a0, &bb0[2]);
            mma16816(acc[0][2], a0, &bb1[0]);
            mma16816(acc[0][3], a0, &bb1[2]);
            mma16816(acc[1][0], a1, &bb0[0]);
            mma16816(acc[1][1], a1, &bb0[2]);
            mma16816(acc[1][2], a1, &bb1[0]);
            mma16816(acc[1][3], a1, &bb1[2]);
        }

        // ---- epilogue: partial z over this warp's 32 cols ----
        // acc[mt] rows: wy*32 + mt*16 + {gid, gid+8}
#pragma unroll
        for (int mt = 0; mt < 2; mt++) {
            float z0 = 0.f, z1 = 0.f;
#pragma unroll
            for (int g = 0; g < 4; g++) {
                int c0 = wx * 32 + g * 8 + tig * 2;
                float2 bw0 = sBW[c0];
                float2 bw1 = sBW[c0 + 1];
                z0 = fmaf(fmaxf(acc[mt][g][0] + bw0.x, 0.f), bw0.y, z0);
                z0 = fmaf(fmaxf(acc[mt][g][1] + bw1.x, 0.f), bw1.y, z0);
                z1 = fmaf(fmaxf(acc[mt][g][2] + bw0.x, 0.f), bw0.y, z1);
                z1 = fmaf(fmaxf(acc[mt][g][3] + bw1.x, 0.f), bw1.y, z1);
            }
            z0 += __shfl_xor_sync(0xffffffffu, z0, 1);
            z0 += __shfl_xor_sync(0xffffffffu, z0, 2);
            z1 += __shfl_xor_sync(0xffffffffu, z1, 1);
            z1 += __shfl_xor_sync(0xffffffffu, z1, 2);
            if (tig == 0) {
                int rr = wy * 32 + mt * 16 + gid;      // 0..63, each once
                sZp[rr * 4 + wx]       = z0;
                sZp[(rr + 8) * 4 + wx] = z1;
            }
        }
        __syncthreads();
    }
    // combine last tile
    if (tid < 64) {
        float z = sZp[tid * 4] + sZp[tid * 4 + 1] + sZp[tid * 4 + 2] +
                  sZp[tid * 4 + 3] + bias3;
        int isel = tid >> 5;
        sEw[isel * 512 + 480 + (tid & 31)] = 1.f / (1.f + expf(-z));
    }
    __syncthreads();

    // ---- softmax per query row g ----
#pragma unroll
    for (int g = 0; g < 2; g++) {
        const int ii = i0 + g;
        const float* ba = base_adj + ((size_t)(b * NN + ii)) * NN;
        float* ew = sEw + g * 512;
        int ja = tid, jb = tid + 256;
        float v0 = ba[ja] * ew[ja] + (ja == ii ? 1.f : 0.f);
        float v1 = ba[jb] * ew[jb] + (jb == ii ? 1.f : 0.f);

        float m = fmaxf(v0, v1);
#pragma unroll
        for (int off = 16; off > 0; off >>= 1)
            m = fmaxf(m, __shfl_xor_sync(0xffffffffu, m, off));
        if (lid == 0) sRed[wid] = m;
        __syncthreads();
        if (tid == 0) {
            float mm = sRed[0];
#pragma unroll
            for (int w = 1; w < 8; w++) mm = fmaxf(mm, sRed[w]);
            sRed[0] = mm;
        }
        __syncthreads();
        m = sRed[0];
        __syncthreads();

        float e0 = expf(v0 - m);
        float e1 = expf(v1 - m);
        float s = e0 + e1;
#pragma unroll
        for (int off = 16; off > 0; off >>= 1)
            s += __shfl_xor_sync(0xffffffffu, s, off);
        if (lid == 0) sRed[wid] = s;
        __syncthreads();
        if (tid == 0) {
            float ss = 0.f;
#pragma unroll
            for (int w = 0; w < 8; w++) ss += sRed[w];
            sRed[0] = ss;
        }
        __syncthreads();
        const float inv = 1.f / sRed[0];
        ew[ja] = e0 * inv;
        ew[jb] = e1 * inv;
        __syncthreads();
    }

    // ---- agg: fp16 x, both query rows share each load ----
    {
        const __half* xb = g_x_h + (size_t)b * NN * DD;
        float a00 = 0.f, a01 = 0.f, a02 = 0.f, a03 = 0.f;
        float a10 = 0.f, a11 = 0.f, a12 = 0.f, a13 = 0.f;
#pragma unroll 2
        for (int j = 0; j < NN; j += 4) {
            float x0 = __half2float(xb[(j)     * DD + tid]);
            float x1 = __half2float(xb[(j + 1) * DD + tid]);
            float x2 = __half2float(xb[(j + 2) * DD + tid]);
            float x3 = __half2float(xb[(j + 3) * DD + tid]);
            a00 = fmaf(sEw[j],           x0, a00);
            a01 = fmaf(sEw[j + 1],       x1, a01);
            a02 = fmaf(sEw[j + 2],       x2, a02);
            a03 = fmaf(sEw[j + 3],       x3, a03);
            a10 = fmaf(sEw[512 + j],     x0, a10);
            a11 = fmaf(sEw[512 + j + 1], x1, a11);
            a12 = fmaf(sEw[512 + j + 2], x2, a12);
            a13 = fmaf(sEw[512 + j + 3], x3, a13);
        }
        sAgg[tid]       = (a00 + a01) + (a02 + a03);
        sAgg[256 + tid] = (a10 + a11) + (a12 + a13);
    }
    __syncthreads();

    // ---- out rows i0,i1 share each Wg load ----
    {
        float o00 = bg[tid], o01 = 0.f, o02 = 0.f, o03 = 0.f;
        float o10 = bg[tid], o11 = 0.f, o12 = 0.f, o13 = 0.f;
#pragma unroll 2
        for (int d = 0; d < DD; d += 4) {
            float w0 = Wg[(d)     * HH + tid];
            float w1 = Wg[(d + 1) * HH + tid];
            float w2 = Wg[(d + 2) * HH + tid];
            float w3v = Wg[(d + 3) * HH + tid];
            o00 = fmaf(sAgg[d],           w0, o00);
            o01 = fmaf(sAgg[d + 1],       w1, o01);
            o02 = fmaf(sAgg[d + 2],       w2, o02);
            o03 = fmaf(sAgg[d + 3],       w3v, o03);
            o10 = fmaf(sAgg[256 + d],     w0, o10);
            o11 = fmaf(sAgg[256 + d + 1], w1, o11);
            o12 = fmaf(sAgg[256 + d + 2], w2, o12);
            o13 = fmaf(sAgg[256 + d + 3], w3v, o13);
        }
        out[((size_t)(b * NN + i0)) * HH + tid]     = (o00 + o01) + (o02 + o03);
        out[((size_t)(b * NN + i0 + 1)) * HH + tid] = (o10 + o11) + (o12 + o13);
    }
}

// ---------------------------------------------------------------------------
extern "C" void kernel_launch(void* const* d_in, const int* in_sizes, int n_in,
                              void* d_out, int out_size)
{
    const float* x        = (const float*)d_in[0];
    const float* base_adj = (const float*)d_in[1];
    const float* W1       = (const float*)d_in[2];
    const float* b1       = (const float*)d_in[3];
    const float* W2       = (const float*)d_in[4];
    const float* b2       = (const float*)d_in[5];
    const float* W3       = (const float*)d_in[6];
    const float* b3       = (const float*)d_in[7];
    const float* Wg       = (const float*)d_in[8];
    const float* bg       = (const float*)d_in[9];
    float* out = (float*)d_out;

    cudaFuncSetAttribute(main_kernel,
                         cudaFuncAttributeMaxDynamicSharedMemorySize,
                         SMEM_TOTAL);

    bprep_kernel<<<64, 256>>>(W2);
    lr_kernel<<<BB * NN / LR_ROWS, 256>>>(x, W1, b1);
    main_kernel<<<dim3(NN / 2, BB), NTHREADS, SMEM_TOTAL>>>(
        base_adj, b2, W3, b3, Wg, bg, out);
}